// round 9
// baseline (speedup 1.0000x reference)
#include <cuda_runtime.h>
#include <cuda_fp16.h>
#include <math.h>
#include <stdint.h>

// ---------------- problem constants ----------------
#define BB 64
#define SS 2048
#define HH 512
#define MM (BB * SS)            // 131072 rows
#define BM 64
#define BN 512
#define BK 64
#define NKC (HH / BK)           // 8 k-chunks

#define SCHUNK 128
#define NCHUNK (SS / SCHUNK)    // 16

// SMEM layout (bytes). Rows padded to 144 B -> conflict-free ldmatrix phases.
#define RS    144
#define AOFF  0
#define BOFF  (BM * RS)             // 9216
#define STAGE ((BM + BN) * RS)      // 82944
#define REDOFF (2 * STAGE)          // 165888
#define SMTOTAL (REDOFF + BM * 16 * 4)  // 169984

// ---------------- scratch (static device mem) ----------------
__device__ float g_part[MM];
__device__ float g_attn[MM];
__device__ float g_pout[BB * NCHUNK * HH];
__device__ __half g_Wh[HH * HH];    // Wt[n,k] = fp16(W[k,n])

// ---------------- helpers ----------------
__device__ __forceinline__ uint32_t smem_u32(const void* p) {
    uint32_t a;
    asm("{ .reg .u64 t; cvta.to.shared.u64 t, %1; cvt.u32.u64 %0, t; }"
        : "=r"(a) : "l"(p));
    return a;
}
__device__ __forceinline__ void cpa16(uint32_t dst, const void* src) {
    asm volatile("cp.async.cg.shared.global [%0], [%1], 16;"
                 :: "r"(dst), "l"(src) : "memory");
}
__device__ __forceinline__ void mma_f16(float* d, const uint32_t* a, const uint32_t* b) {
    asm volatile("mma.sync.aligned.m16n8k16.row.col.f32.f16.f16.f32 "
                 "{%0,%1,%2,%3}, {%4,%5,%6,%7}, {%8,%9}, {%0,%1,%2,%3};"
                 : "+f"(d[0]), "+f"(d[1]), "+f"(d[2]), "+f"(d[3])
                 : "r"(a[0]), "r"(a[1]), "r"(a[2]), "r"(a[3]),
                   "r"(b[0]), "r"(b[1]));
}
__device__ __forceinline__ void ldsm4(uint32_t& r0, uint32_t& r1, uint32_t& r2,
                                      uint32_t& r3, uint32_t addr) {
    asm volatile("ldmatrix.sync.aligned.m8n8.x4.shared.b16 {%0,%1,%2,%3}, [%4];"
                 : "=r"(r0), "=r"(r1), "=r"(r2), "=r"(r3) : "r"(addr));
}
__device__ __forceinline__ uint32_t pack_h2(float x, float y) {
    __half2 h = __floats2half2_rn(x, y);
    return *(uint32_t*)&h;
}

// ---------------------------------------------------------------------------
// W prep: transpose + fp16 round.  Wt[n,k] = fp16(W[k,n])
// ---------------------------------------------------------------------------
__global__ void prep_w(const float* __restrict__ W) {
    __shared__ float t[32][33];
    int n0 = blockIdx.x * 32, k0 = blockIdx.y * 32;
    int tx = threadIdx.x, ty = threadIdx.y;      // 32 x 8
    #pragma unroll
    for (int r = 0; r < 32; r += 8)
        t[ty + r][tx] = W[(size_t)(k0 + ty + r) * HH + n0 + tx];
    __syncthreads();
    #pragma unroll
    for (int r = 0; r < 32; r += 8) {
        int n = n0 + ty + r, k = k0 + tx;
        g_Wh[(size_t)n * HH + k] = __float2half_rn(t[tx][ty + r]);
    }
}

// ---------------------------------------------------------------------------
// fp16 HMMA GEMM, single N-pass (BN=512). X read fp32 ONCE.
// A staging split: LDG->regs issued a chunk ahead; cvt+STS after compute.
// grid (MM/BM) = 2048, 512 threads (16 warps across N, warp tile 64x32).
// ---------------------------------------------------------------------------
__global__ __launch_bounds__(512, 1) void gemm_score_mma(
    const float* __restrict__ A, const float* __restrict__ bias,
    const float* __restrict__ wat)
{
    extern __shared__ char sm[];
    const uint32_t sbase = smem_u32(sm);
    const int tid = threadIdx.x, lane = tid & 31, wid = tid >> 5;
    const int g = lane >> 2, tig = lane & 3;
    const int wn = wid;                     // 16 warps across N
    const int m0 = blockIdx.x * BM;

    // A fill mapping: r = tid>>3 (0..63), seg = tid&7 (0..7) -> 8 floats
    const int ar = tid >> 3, aseg = tid & 7;
    const float* arow = &A[(size_t)(m0 + ar) * HH + aseg * 8];

    // ldmatrix lane-address offsets (within a stage)
    const uint32_t boff = (uint32_t)(BOFF + (wn * 32 + ((lane >> 4) * 8) + (lane & 7)) * RS
                                     + (((lane >> 3) & 1) * 16));
    const uint32_t aoff = (uint32_t)(AOFF + ((((lane >> 3) & 1) * 8) + (lane & 7)) * RS
                                     + ((lane >> 4) * 16));

    float acc[4][4][4] = {};   // [mi][ni][frag]
    float4 rA0, rA1;           // A chunk staged in registers

    // B fill: 512 rows x 8 segs = 4096 cp.async / 512 threads = 8 each
    auto fillB = [&](int c, uint32_t st) {
        const int k0 = c * BK;
        #pragma unroll
        for (int t = 0; t < 8; t++) {
            int i = tid + t * 512;
            int r = i >> 3, seg = i & 7;
            cpa16(st + BOFF + r * RS + seg * 16,
                  g_Wh + (size_t)r * HH + k0 + seg * 8);
        }
        asm volatile("cp.async.commit_group;" ::: "memory");
    };
    auto ldA = [&](int c) {
        const float* p = arow + c * BK;
        rA0 = *(const float4*)p;
        rA1 = *(const float4*)(p + 4);
    };
    auto stsA = [&](uint32_t stoff) {
        uint4 hp = make_uint4(pack_h2(rA0.x, rA0.y), pack_h2(rA0.z, rA0.w),
                              pack_h2(rA1.x, rA1.y), pack_h2(rA1.z, rA1.w));
        *(uint4*)(sm + stoff + AOFF + ar * RS + aseg * 16) = hp;
    };

    // ---- prologue: chunk 0 ----
    ldA(0);
    fillB(0, sbase);
    stsA(0);
    asm volatile("cp.async.wait_group 0;" ::: "memory");
    __syncthreads();

    for (int c = 0; c < NKC; c++) {
        const int pb = c & 1, nb = pb ^ 1;
        if (c + 1 < NKC) {
            ldA(c + 1);                      // LDG in flight during compute
            fillB(c + 1, sbase + nb * STAGE);
        }

        const uint32_t st = sbase + pb * STAGE;
        #pragma unroll
        for (int ks = 0; ks < 4; ks++) {
            const uint32_t kso = (uint32_t)(ks * 32);
            uint32_t bh[4][2];
            ldsm4(bh[0][0], bh[0][1], bh[1][0], bh[1][1], st + boff + kso);
            ldsm4(bh[2][0], bh[2][1], bh[3][0], bh[3][1], st + boff + kso + 16 * RS);
            #pragma unroll
            for (int mi = 0; mi < 4; mi++) {
                uint32_t ah[4];
                ldsm4(ah[0], ah[1], ah[2], ah[3],
                      st + aoff + (uint32_t)(mi * 16 * RS) + kso);
                #pragma unroll
                for (int ni = 0; ni < 4; ni++)
                    mma_f16(acc[mi][ni], ah, bh[ni]);
            }
        }

        if (c + 1 < NKC) {
            stsA((uint32_t)(nb * STAGE));    // regs ready; STS cheap
            asm volatile("cp.async.wait_group 0;" ::: "memory");
            __syncthreads();
        }
    }

    // ---- epilogue: tanh(z + b) * w, reduce over ALL 512 columns ----
    float* red = (float*)(sm + REDOFF);   // [64 rows][16 warps]
    #pragma unroll
    for (int mi = 0; mi < 4; mi++) {
        float s0 = 0.f, s1 = 0.f;
        #pragma unroll
        for (int ni = 0; ni < 4; ni++) {
            int col = wn * 32 + ni * 8 + tig * 2;
            float2 bb = *(const float2*)&bias[col];
            float2 ww = *(const float2*)&wat[col];
            s0 += tanhf(acc[mi][ni][0] + bb.x) * ww.x
                + tanhf(acc[mi][ni][1] + bb.y) * ww.y;
            s1 += tanhf(acc[mi][ni][2] + bb.x) * ww.x
                + tanhf(acc[mi][ni][3] + bb.y) * ww.y;
        }
        s0 += __shfl_down_sync(0xFFFFFFFFu, s0, 2, 4);
        s0 += __shfl_down_sync(0xFFFFFFFFu, s0, 1, 4);
        s1 += __shfl_down_sync(0xFFFFFFFFu, s1, 2, 4);
        s1 += __shfl_down_sync(0xFFFFFFFFu, s1, 1, 4);
        if (tig == 0) {
            red[(mi * 16 + g) * 16 + wn]     = s0;
            red[(mi * 16 + 8 + g) * 16 + wn] = s1;
        }
    }
    __syncthreads();
    if (tid < BM) {
        const float* r = red + tid * 16;
        float v = 0.f;
        #pragma unroll
        for (int j = 0; j < 16; j++) v += r[j];
        g_part[(size_t)m0 + tid] = v;
    }
}

// ---------------------------------------------------------------------------
// softmax over full sequence, then mask + renormalize.
// ---------------------------------------------------------------------------
__global__ __launch_bounds__(256) void softmax_kernel(const int* __restrict__ seqlen)
{
    __shared__ float sc[SS];
    __shared__ float red[256];
    __shared__ float red2[256];

    const int b = blockIdx.x, tid = threadIdx.x;
    const int len = seqlen[b];

    for (int s = tid; s < SS; s += 256)
        sc[s] = g_part[(size_t)b * SS + s];
    __syncthreads();

    float m = -INFINITY;
    for (int s = tid; s < SS; s += 256) m = fmaxf(m, sc[s]);
    red[tid] = m;
    __syncthreads();
    for (int o = 128; o > 0; o >>= 1) {
        if (tid < o) red[tid] = fmaxf(red[tid], red[tid + o]);
        __syncthreads();
    }
    m = red[0];
    __syncthreads();

    float z = 0.f, zm = 0.f;
    for (int s = tid; s < SS; s += 256) {
        float e = expf(sc[s] - m);
        z += e;
        if (s < len) zm += e;
    }
    red[tid] = z; red2[tid] = zm;
    __syncthreads();
    for (int o = 128; o > 0; o >>= 1) {
        if (tid < o) { red[tid] += red[tid + o]; red2[tid] += red2[tid + o]; }
        __syncthreads();
    }
    z = red[0]; zm = red2[0];

    const float inv = 1.f / (zm + 1e-6f * z);
    for (int s = tid; s < SS; s += 256) {
        float e = (s < len) ? expf(sc[s] - m) * inv : 0.f;
        g_attn[(size_t)b * SS + s] = e;
    }
}

// ---------------------------------------------------------------------------
// pooling partials (4 independent accumulators) + reduce
// ---------------------------------------------------------------------------
__global__ __launch_bounds__(HH) void pool_kernel(
    const float* __restrict__ X, const int* __restrict__ seqlen)
{
    const int b = blockIdx.x, c = blockIdx.y, h = threadIdx.x;
    const int s0 = c * SCHUNK;
    const int len = seqlen[b];

    __shared__ float at[SCHUNK];
    if (h < SCHUNK) at[h] = g_attn[(size_t)b * SS + s0 + h];
    __syncthreads();

    int end = len - s0;
    if (end > SCHUNK) end = SCHUNK;
    float a0 = 0.f, a1 = 0.f, a2 = 0.f, a3 = 0.f;
    if (end > 0) {
        const float* xp = &X[((size_t)b * SS + s0) * HH + h];
        int s = 0;
        for (; s + 3 < end; s += 4) {
            a0 = fmaf(xp[(size_t)(s + 0) * HH], at[s + 0], a0);
            a1 = fmaf(xp[(size_t)(s + 1) * HH], at[s + 1], a1);
            a2 = fmaf(xp[(size_t)(s + 2) * HH], at[s + 2], a2);
            a3 = fmaf(xp[(size_t)(s + 3) * HH], at[s + 3], a3);
        }
        for (; s < end; s++)
            a0 = fmaf(xp[(size_t)s * HH], at[s], a0);
    }
    g_pout[((size_t)b * NCHUNK + c) * HH + h] = (a0 + a1) + (a2 + a3);
}

__global__ __launch_bounds__(256) void reduce_out_kernel(float* __restrict__ out)
{
    int i = blockIdx.x * blockDim.x + threadIdx.x;
    if (i >= BB * HH) return;
    int b = i / HH, h = i % HH;
    float v = 0.f;
    #pragma unroll
    for (int c = 0; c < NCHUNK; c++)
        v += g_pout[((size_t)b * NCHUNK + c) * HH + h];
    out[i] = v;
}

// ---------------------------------------------------------------------------
extern "C" void kernel_launch(void* const* d_in, const int* in_sizes, int n_in,
                              void* d_out, int out_size)
{
    const float* X      = (const float*)d_in[0];
    const int*   seqlen = (const int*)  d_in[1];
    const float* W      = (const float*)d_in[2];
    const float* bias   = (const float*)d_in[3];
    const float* wat    = (const float*)d_in[4];
    float*       out    = (float*)d_out;

    cudaFuncSetAttribute(gemm_score_mma,
                         cudaFuncAttributeMaxDynamicSharedMemorySize, SMTOTAL);

    prep_w<<<dim3(16, 16), dim3(32, 8)>>>(W);

    gemm_score_mma<<<MM / BM, 512, SMTOTAL>>>(X, bias, wat);

    softmax_kernel<<<BB, 256>>>(seqlen);

    dim3 gpool(BB, NCHUNK);                  // (64, 16)
    pool_kernel<<<gpool, HH>>>(X, seqlen);

    reduce_out_kernel<<<(BB * HH + 255) / 256, 256>>>(out);
}

// round 10
// speedup vs baseline: 1.0113x; 1.0113x over previous
#include <cuda_runtime.h>
#include <cuda_fp16.h>
#include <math.h>
#include <stdint.h>

// ---------------- problem constants ----------------
#define BB 64
#define SS 2048
#define HH 512
#define MM (BB * SS)            // 131072 rows
#define BM 64
#define BN 256
#define BK 64
#define NKC (HH / BK)           // 8 k-chunks
#define NT  (HH / BN)           // 2 n-tiles

#define SCHUNK 128
#define NCHUNK (SS / SCHUNK)    // 16

// SMEM layout (bytes). Rows padded to 144 B -> conflict-free ldmatrix phases.
#define RS    144
#define AOFF  0
#define BOFF  (BM * RS)             // 9216
#define STAGE ((BM + BN) * RS)      // 46080
#define REDOFF (2 * STAGE)          // 92160
#define SMTOTAL (REDOFF + BM * 8 * 4)   // 94208

// ---------------- scratch (static device mem) ----------------
__device__ float g_part[NT * MM];
__device__ float g_attn[MM];
__device__ float g_pout[BB * NCHUNK * HH];
__device__ __half g_Wh[HH * HH];    // Wt[n,k] = fp16(W[k,n])

// ---------------- helpers ----------------
__device__ __forceinline__ uint32_t smem_u32(const void* p) {
    uint32_t a;
    asm("{ .reg .u64 t; cvta.to.shared.u64 t, %1; cvt.u32.u64 %0, t; }"
        : "=r"(a) : "l"(p));
    return a;
}
__device__ __forceinline__ void cpa16(uint32_t dst, const void* src) {
    asm volatile("cp.async.cg.shared.global [%0], [%1], 16;"
                 :: "r"(dst), "l"(src) : "memory");
}
__device__ __forceinline__ void mma_f16(float* d, const uint32_t* a, const uint32_t* b) {
    asm volatile("mma.sync.aligned.m16n8k16.row.col.f32.f16.f16.f32 "
                 "{%0,%1,%2,%3}, {%4,%5,%6,%7}, {%8,%9}, {%0,%1,%2,%3};"
                 : "+f"(d[0]), "+f"(d[1]), "+f"(d[2]), "+f"(d[3])
                 : "r"(a[0]), "r"(a[1]), "r"(a[2]), "r"(a[3]),
                   "r"(b[0]), "r"(b[1]));
}
__device__ __forceinline__ void ldsm4(uint32_t& r0, uint32_t& r1, uint32_t& r2,
                                      uint32_t& r3, uint32_t addr) {
    asm volatile("ldmatrix.sync.aligned.m8n8.x4.shared.b16 {%0,%1,%2,%3}, [%4];"
                 : "=r"(r0), "=r"(r1), "=r"(r2), "=r"(r3) : "r"(addr));
}
__device__ __forceinline__ uint32_t pack_h2(float x, float y) {
    __half2 h = __floats2half2_rn(x, y);
    return *(uint32_t*)&h;
}

// ---------------------------------------------------------------------------
// W prep: transpose + fp16 round.  Wt[n,k] = fp16(W[k,n])
// ---------------------------------------------------------------------------
__global__ void prep_w(const float* __restrict__ W) {
    __shared__ float t[32][33];
    int n0 = blockIdx.x * 32, k0 = blockIdx.y * 32;
    int tx = threadIdx.x, ty = threadIdx.y;      // 32 x 8
    #pragma unroll
    for (int r = 0; r < 32; r += 8)
        t[ty + r][tx] = W[(size_t)(k0 + ty + r) * HH + n0 + tx];
    __syncthreads();
    #pragma unroll
    for (int r = 0; r < 32; r += 8) {
        int n = n0 + ty + r, k = k0 + tx;
        g_Wh[(size_t)n * HH + k] = __float2half_rn(t[tx][ty + r]);
    }
}

// ---------------------------------------------------------------------------
// fp16 HMMA GEMM, BM=64 x BN=256, BK=64, fp32-A direct with register staging.
// grid (NT, MM/BM) = (2, 2048), 256 threads (8 warps across N), 2 CTAs/SM.
// ---------------------------------------------------------------------------
__global__ __launch_bounds__(256, 2) void gemm_score_mma(
    const float* __restrict__ A, const float* __restrict__ bias,
    const float* __restrict__ wat)
{
    extern __shared__ char sm[];
    const uint32_t sbase = smem_u32(sm);
    const int tid = threadIdx.x, lane = tid & 31, wid = tid >> 5;
    const int g = lane >> 2, tig = lane & 3;
    const int wn = wid;                     // 8 warps across N
    const int m0 = blockIdx.y * BM, n0 = blockIdx.x * BN;

    // A fill mapping: row = tid>>2 (0..63), 16 consecutive floats at (tid&3)*16
    const int ar = tid >> 2, afq = tid & 3;
    const float* arow = &A[(size_t)(m0 + ar) * HH + afq * 16];

    // ldmatrix lane-address offsets (within a stage)
    const uint32_t boff = (uint32_t)(BOFF + (wn * 32 + ((lane >> 4) * 8) + (lane & 7)) * RS
                                     + (((lane >> 3) & 1) * 16));
    const uint32_t aoff = (uint32_t)(AOFF + ((((lane >> 3) & 1) * 8) + (lane & 7)) * RS
                                     + ((lane >> 4) * 16));

    float acc[4][4][4] = {};   // [mi][ni][frag]
    float4 rA[4];              // 16 floats staged in registers

    // B fill: 256 rows x 8 segs = 2048 cp.async / 256 threads = 8 each
    auto fillB = [&](int c, uint32_t st) {
        const int k0 = c * BK;
        #pragma unroll
        for (int t = 0; t < 8; t++) {
            int i = tid + t * 256;
            int r = i >> 3, seg = i & 7;
            cpa16(st + BOFF + r * RS + seg * 16,
                  g_Wh + (size_t)(n0 + r) * HH + k0 + seg * 8);
        }
        asm volatile("cp.async.commit_group;" ::: "memory");
    };
    auto ldA = [&](int c) {
        const float* p = arow + c * BK;
        #pragma unroll
        for (int q = 0; q < 4; q++) rA[q] = *(const float4*)(p + q * 4);
    };
    auto stsA = [&](uint32_t stoff) {
        uint4 h0 = make_uint4(pack_h2(rA[0].x, rA[0].y), pack_h2(rA[0].z, rA[0].w),
                              pack_h2(rA[1].x, rA[1].y), pack_h2(rA[1].z, rA[1].w));
        uint4 h1 = make_uint4(pack_h2(rA[2].x, rA[2].y), pack_h2(rA[2].z, rA[2].w),
                              pack_h2(rA[3].x, rA[3].y), pack_h2(rA[3].z, rA[3].w));
        char* dst = sm + stoff + AOFF + ar * RS + afq * 32;
        *(uint4*)dst = h0;
        *(uint4*)(dst + 16) = h1;
    };

    // ---- prologue: chunk 0 ----
    ldA(0);
    fillB(0, sbase);
    stsA(0);
    asm volatile("cp.async.wait_group 0;" ::: "memory");
    __syncthreads();

    for (int c = 0; c < NKC; c++) {
        const int pb = c & 1, nb = pb ^ 1;
        if (c + 1 < NKC) {
            ldA(c + 1);
            fillB(c + 1, sbase + nb * STAGE);
        }

        const uint32_t st = sbase + pb * STAGE;
        #pragma unroll
        for (int ks = 0; ks < 4; ks++) {
            const uint32_t kso = (uint32_t)(ks * 32);
            uint32_t bh[4][2];
            ldsm4(bh[0][0], bh[0][1], bh[1][0], bh[1][1], st + boff + kso);
            ldsm4(bh[2][0], bh[2][1], bh[3][0], bh[3][1], st + boff + kso + 16 * RS);
            #pragma unroll
            for (int mi = 0; mi < 4; mi++) {
                uint32_t ah[4];
                ldsm4(ah[0], ah[1], ah[2], ah[3],
                      st + aoff + (uint32_t)(mi * 16 * RS) + kso);
                #pragma unroll
                for (int ni = 0; ni < 4; ni++)
                    mma_f16(acc[mi][ni], ah, bh[ni]);
            }
        }

        if (c + 1 < NKC) {
            stsA((uint32_t)(nb * STAGE));
            asm volatile("cp.async.wait_group 0;" ::: "memory");
            __syncthreads();
        }
    }

    // ---- epilogue: tanh(z + b) * w, reduce over this CTA's 256 columns ----
    float* red = (float*)(sm + REDOFF);   // [64 rows][8 warps]
    #pragma unroll
    for (int mi = 0; mi < 4; mi++) {
        float s0 = 0.f, s1 = 0.f;
        #pragma unroll
        for (int ni = 0; ni < 4; ni++) {
            int col = n0 + wn * 32 + ni * 8 + tig * 2;
            float2 bb = *(const float2*)&bias[col];
            float2 ww = *(const float2*)&wat[col];
            s0 += tanhf(acc[mi][ni][0] + bb.x) * ww.x
                + tanhf(acc[mi][ni][1] + bb.y) * ww.y;
            s1 += tanhf(acc[mi][ni][2] + bb.x) * ww.x
                + tanhf(acc[mi][ni][3] + bb.y) * ww.y;
        }
        s0 += __shfl_down_sync(0xFFFFFFFFu, s0, 2, 4);
        s0 += __shfl_down_sync(0xFFFFFFFFu, s0, 1, 4);
        s1 += __shfl_down_sync(0xFFFFFFFFu, s1, 2, 4);
        s1 += __shfl_down_sync(0xFFFFFFFFu, s1, 1, 4);
        if (tig == 0) {
            red[(mi * 16 + g) * 8 + wn]     = s0;
            red[(mi * 16 + 8 + g) * 8 + wn] = s1;
        }
    }
    __syncthreads();
    if (tid < BM) {
        const float* r = red + tid * 8;
        float v = ((r[0] + r[1]) + (r[2] + r[3])) + ((r[4] + r[5]) + (r[6] + r[7]));
        g_part[(size_t)blockIdx.x * MM + m0 + tid] = v;
    }
}

// ---------------------------------------------------------------------------
// softmax over full sequence, then mask + renormalize.
// ---------------------------------------------------------------------------
__global__ __launch_bounds__(256) void softmax_kernel(const int* __restrict__ seqlen)
{
    __shared__ float sc[SS];
    __shared__ float red[256];
    __shared__ float red2[256];

    const int b = blockIdx.x, tid = threadIdx.x;
    const int len = seqlen[b];

    for (int s = tid; s < SS; s += 256) {
        float v = 0.f;
        #pragma unroll
        for (int j = 0; j < NT; j++)
            v += g_part[(size_t)j * MM + (size_t)b * SS + s];
        sc[s] = v;
    }
    __syncthreads();

    float m = -INFINITY;
    for (int s = tid; s < SS; s += 256) m = fmaxf(m, sc[s]);
    red[tid] = m;
    __syncthreads();
    for (int o = 128; o > 0; o >>= 1) {
        if (tid < o) red[tid] = fmaxf(red[tid], red[tid + o]);
        __syncthreads();
    }
    m = red[0];
    __syncthreads();

    float z = 0.f, zm = 0.f;
    for (int s = tid; s < SS; s += 256) {
        float e = expf(sc[s] - m);
        z += e;
        if (s < len) zm += e;
    }
    red[tid] = z; red2[tid] = zm;
    __syncthreads();
    for (int o = 128; o > 0; o >>= 1) {
        if (tid < o) { red[tid] += red[tid + o]; red2[tid] += red2[tid + o]; }
        __syncthreads();
    }
    z = red[0]; zm = red2[0];

    const float inv = 1.f / (zm + 1e-6f * z);
    for (int s = tid; s < SS; s += 256) {
        float e = (s < len) ? expf(sc[s] - m) * inv : 0.f;
        g_attn[(size_t)b * SS + s] = e;
    }
}

// ---------------------------------------------------------------------------
// pooling partials (4 independent accumulators) + reduce
// ---------------------------------------------------------------------------
__global__ __launch_bounds__(HH) void pool_kernel(
    const float* __restrict__ X, const int* __restrict__ seqlen)
{
    const int b = blockIdx.x, c = blockIdx.y, h = threadIdx.x;
    const int s0 = c * SCHUNK;
    const int len = seqlen[b];

    __shared__ float at[SCHUNK];
    if (h < SCHUNK) at[h] = g_attn[(size_t)b * SS + s0 + h];
    __syncthreads();

    int end = len - s0;
    if (end > SCHUNK) end = SCHUNK;
    float a0 = 0.f, a1 = 0.f, a2 = 0.f, a3 = 0.f;
    if (end > 0) {
        const float* xp = &X[((size_t)b * SS + s0) * HH + h];
        int s = 0;
        for (; s + 3 < end; s += 4) {
            a0 = fmaf(xp[(size_t)(s + 0) * HH], at[s + 0], a0);
            a1 = fmaf(xp[(size_t)(s + 1) * HH], at[s + 1], a1);
            a2 = fmaf(xp[(size_t)(s + 2) * HH], at[s + 2], a2);
            a3 = fmaf(xp[(size_t)(s + 3) * HH], at[s + 3], a3);
        }
        for (; s < end; s++)
            a0 = fmaf(xp[(size_t)s * HH], at[s], a0);
    }
    g_pout[((size_t)b * NCHUNK + c) * HH + h] = (a0 + a1) + (a2 + a3);
}

__global__ __launch_bounds__(256) void reduce_out_kernel(float* __restrict__ out)
{
    int i = blockIdx.x * blockDim.x + threadIdx.x;
    if (i >= BB * HH) return;
    int b = i / HH, h = i % HH;
    float v = 0.f;
    #pragma unroll
    for (int c = 0; c < NCHUNK; c++)
        v += g_pout[((size_t)b * NCHUNK + c) * HH + h];
    out[i] = v;
}

// ---------------------------------------------------------------------------
extern "C" void kernel_launch(void* const* d_in, const int* in_sizes, int n_in,
                              void* d_out, int out_size)
{
    const float* X      = (const float*)d_in[0];
    const int*   seqlen = (const int*)  d_in[1];
    const float* W      = (const float*)d_in[2];
    const float* bias   = (const float*)d_in[3];
    const float* wat    = (const float*)d_in[4];
    float*       out    = (float*)d_out;

    cudaFuncSetAttribute(gemm_score_mma,
                         cudaFuncAttributeMaxDynamicSharedMemorySize, SMTOTAL);

    prep_w<<<dim3(16, 16), dim3(32, 8)>>>(W);

    dim3 ggemm(NT, MM / BM);                 // (2, 2048)
    gemm_score_mma<<<ggemm, 256, SMTOTAL>>>(X, bias, wat);

    softmax_kernel<<<BB, 256>>>(seqlen);

    dim3 gpool(BB, NCHUNK);                  // (64, 16)
    pool_kernel<<<gpool, HH>>>(X, seqlen);

    reduce_out_kernel<<<(BB * HH + 255) / 256, 256>>>(out);
}

// round 11
// speedup vs baseline: 1.0994x; 1.0871x over previous
#include <cuda_runtime.h>
#include <cuda_fp16.h>
#include <math.h>
#include <stdint.h>

// ---------------- problem constants ----------------
#define BB 64
#define SS 2048
#define HH 512
#define MM (BB * SS)            // 131072 rows
#define BM 64
#define BN 512
#define BK 64
#define NKC (HH / BK)           // 8 k-chunks

#define SCHUNK 128
#define NCHUNK (SS / SCHUNK)    // 16

// SMEM layout (bytes). Rows padded to 144 B -> conflict-free ldmatrix phases.
#define RS    144
#define AOFF  0
#define BOFF  (BM * RS)             // 9216
#define STAGE ((BM + BN) * RS)      // 82944
#define REDOFF (2 * STAGE)          // 165888
#define SMTOTAL (REDOFF + BM * 16 * 4)  // 169984

// ---------------- scratch (static device mem) ----------------
__device__ float g_part[MM];
__device__ float g_attn[MM];
__device__ float g_pout[BB * NCHUNK * HH];
__device__ __half g_Wh[HH * HH];    // Wt[n,k] = fp16(W[k,n])

// ---------------- helpers ----------------
__device__ __forceinline__ uint32_t smem_u32(const void* p) {
    uint32_t a;
    asm("{ .reg .u64 t; cvta.to.shared.u64 t, %1; cvt.u32.u64 %0, t; }"
        : "=r"(a) : "l"(p));
    return a;
}
__device__ __forceinline__ void cpa16(uint32_t dst, const void* src) {
    asm volatile("cp.async.cg.shared.global [%0], [%1], 16;"
                 :: "r"(dst), "l"(src) : "memory");
}
__device__ __forceinline__ void mma_f16(float* d, const uint32_t* a, const uint32_t* b) {
    asm volatile("mma.sync.aligned.m16n8k16.row.col.f32.f16.f16.f32 "
                 "{%0,%1,%2,%3}, {%4,%5,%6,%7}, {%8,%9}, {%0,%1,%2,%3};"
                 : "+f"(d[0]), "+f"(d[1]), "+f"(d[2]), "+f"(d[3])
                 : "r"(a[0]), "r"(a[1]), "r"(a[2]), "r"(a[3]),
                   "r"(b[0]), "r"(b[1]));
}
__device__ __forceinline__ void ldsm4(uint32_t& r0, uint32_t& r1, uint32_t& r2,
                                      uint32_t& r3, uint32_t addr) {
    asm volatile("ldmatrix.sync.aligned.m8n8.x4.shared.b16 {%0,%1,%2,%3}, [%4];"
                 : "=r"(r0), "=r"(r1), "=r"(r2), "=r"(r3) : "r"(addr));
}
__device__ __forceinline__ uint32_t pack_h2(float x, float y) {
    __half2 h = __floats2half2_rn(x, y);
    return *(uint32_t*)&h;
}
__device__ __forceinline__ float tanh_fast(float x) {
    float y;
    asm("tanh.approx.f32 %0, %1;" : "=f"(y) : "f"(x));
    return y;
}

// ---------------------------------------------------------------------------
// W prep: transpose + fp16 round.  Wt[n,k] = fp16(W[k,n])
// ---------------------------------------------------------------------------
__global__ void prep_w(const float* __restrict__ W) {
    __shared__ float t[32][33];
    int n0 = blockIdx.x * 32, k0 = blockIdx.y * 32;
    int tx = threadIdx.x, ty = threadIdx.y;      // 32 x 8
    #pragma unroll
    for (int r = 0; r < 32; r += 8)
        t[ty + r][tx] = W[(size_t)(k0 + ty + r) * HH + n0 + tx];
    __syncthreads();
    #pragma unroll
    for (int r = 0; r < 32; r += 8) {
        int n = n0 + ty + r, k = k0 + tx;
        g_Wh[(size_t)n * HH + k] = __float2half_rn(t[tx][ty + r]);
    }
}

// ---------------------------------------------------------------------------
// fp16 HMMA GEMM, single N-pass (BN=512). X read fp32 ONCE, cvt in-register.
// grid (MM/BM) = 2048, 512 threads (16 warps across N, warp tile 64x32).
// Mainloop structure identical to the best-measured R8 variant.
// ---------------------------------------------------------------------------
__global__ __launch_bounds__(512, 1) void gemm_score_mma(
    const float* __restrict__ A, const float* __restrict__ bias,
    const float* __restrict__ wat)
{
    extern __shared__ char sm[];
    const uint32_t sbase = smem_u32(sm);
    const int tid = threadIdx.x, lane = tid & 31, wid = tid >> 5;
    const int g = lane >> 2, tig = lane & 3;
    const int wn = wid;                     // 16 warps across N
    const int m0 = blockIdx.x * BM;

    // A fill mapping: r = tid>>3 (0..63), seg = tid&7 (0..7) -> 8 floats
    const int ar = tid >> 3, aseg = tid & 7;

    // ldmatrix lane-address offsets (within a stage)
    const uint32_t boff = (uint32_t)(BOFF + (wn * 32 + ((lane >> 4) * 8) + (lane & 7)) * RS
                                     + (((lane >> 3) & 1) * 16));
    const uint32_t aoff = (uint32_t)(AOFF + ((((lane >> 3) & 1) * 8) + (lane & 7)) * RS
                                     + ((lane >> 4) * 16));

    float acc[4][4][4] = {};   // [mi][ni][frag]

    // fill: A (fp32 load + cvt + STS), B (cp.async), one chunk into stage st
    auto fill = [&](int c, uint32_t st) {
        const int k0 = c * BK;
        #pragma unroll
        for (int t = 0; t < 8; t++) {
            int i = tid + t * 512;
            int r = i >> 3, seg = i & 7;
            cpa16(st + BOFF + r * RS + seg * 16,
                  g_Wh + (size_t)r * HH + k0 + seg * 8);
        }
        asm volatile("cp.async.commit_group;" ::: "memory");
        const float* p = &A[(size_t)(m0 + ar) * HH + k0 + aseg * 8];
        float4 v0 = *(const float4*)p;
        float4 v1 = *(const float4*)(p + 4);
        uint4 hp = make_uint4(pack_h2(v0.x, v0.y), pack_h2(v0.z, v0.w),
                              pack_h2(v1.x, v1.y), pack_h2(v1.z, v1.w));
        *(uint4*)(sm + (st - sbase) + AOFF + ar * RS + aseg * 16) = hp;
    };

    fill(0, sbase);
    asm volatile("cp.async.wait_group 0;" ::: "memory");
    __syncthreads();

    for (int c = 0; c < NKC; c++) {
        const int pb = c & 1, nb = pb ^ 1;
        if (c + 1 < NKC) fill(c + 1, sbase + nb * STAGE);

        const uint32_t st = sbase + pb * STAGE;
        #pragma unroll
        for (int ks = 0; ks < 4; ks++) {
            const uint32_t kso = (uint32_t)(ks * 32);
            uint32_t bh[4][2];
            ldsm4(bh[0][0], bh[0][1], bh[1][0], bh[1][1], st + boff + kso);
            ldsm4(bh[2][0], bh[2][1], bh[3][0], bh[3][1], st + boff + kso + 16 * RS);
            #pragma unroll
            for (int mi = 0; mi < 4; mi++) {
                uint32_t ah[4];
                ldsm4(ah[0], ah[1], ah[2], ah[3],
                      st + aoff + (uint32_t)(mi * 16 * RS) + kso);
                #pragma unroll
                for (int ni = 0; ni < 4; ni++)
                    mma_f16(acc[mi][ni], ah, bh[ni]);
            }
        }

        if (c + 1 < NKC) {
            asm volatile("cp.async.wait_group 0;" ::: "memory");
            __syncthreads();
        }
    }

    // ---- epilogue: tanh.approx(z + b) * w, reduce over ALL 512 columns ----
    // bias/w are mi-invariant per thread: hoist loads.
    float bbx[4], bby[4], wwx[4], wwy[4];
    #pragma unroll
    for (int ni = 0; ni < 4; ni++) {
        int col = wn * 32 + ni * 8 + tig * 2;
        float2 bb = *(const float2*)&bias[col];
        float2 ww = *(const float2*)&wat[col];
        bbx[ni] = bb.x; bby[ni] = bb.y; wwx[ni] = ww.x; wwy[ni] = ww.y;
    }
    float* red = (float*)(sm + REDOFF);   // [64 rows][16 warps]
    #pragma unroll
    for (int mi = 0; mi < 4; mi++) {
        float s0 = 0.f, s1 = 0.f;
        #pragma unroll
        for (int ni = 0; ni < 4; ni++) {
            s0 += tanh_fast(acc[mi][ni][0] + bbx[ni]) * wwx[ni]
                + tanh_fast(acc[mi][ni][1] + bby[ni]) * wwy[ni];
            s1 += tanh_fast(acc[mi][ni][2] + bbx[ni]) * wwx[ni]
                + tanh_fast(acc[mi][ni][3] + bby[ni]) * wwy[ni];
        }
        s0 += __shfl_down_sync(0xFFFFFFFFu, s0, 2, 4);
        s0 += __shfl_down_sync(0xFFFFFFFFu, s0, 1, 4);
        s1 += __shfl_down_sync(0xFFFFFFFFu, s1, 2, 4);
        s1 += __shfl_down_sync(0xFFFFFFFFu, s1, 1, 4);
        if (tig == 0) {
            red[(mi * 16 + g) * 16 + wn]     = s0;
            red[(mi * 16 + 8 + g) * 16 + wn] = s1;
        }
    }
    __syncthreads();
    if (tid < BM) {
        const float* r = red + tid * 16;
        float v = 0.f;
        #pragma unroll
        for (int j = 0; j < 16; j++) v += r[j];
        g_part[(size_t)m0 + tid] = v;
    }
}

// ---------------------------------------------------------------------------
// softmax over full sequence, then mask + renormalize.
// ---------------------------------------------------------------------------
__global__ __launch_bounds__(256) void softmax_kernel(const int* __restrict__ seqlen)
{
    __shared__ float sc[SS];
    __shared__ float red[256];
    __shared__ float red2[256];

    const int b = blockIdx.x, tid = threadIdx.x;
    const int len = seqlen[b];

    for (int s = tid; s < SS; s += 256)
        sc[s] = g_part[(size_t)b * SS + s];
    __syncthreads();

    float m = -INFINITY;
    for (int s = tid; s < SS; s += 256) m = fmaxf(m, sc[s]);
    red[tid] = m;
    __syncthreads();
    for (int o = 128; o > 0; o >>= 1) {
        if (tid < o) red[tid] = fmaxf(red[tid], red[tid + o]);
        __syncthreads();
    }
    m = red[0];
    __syncthreads();

    float z = 0.f, zm = 0.f;
    for (int s = tid; s < SS; s += 256) {
        float e = expf(sc[s] - m);
        z += e;
        if (s < len) zm += e;
    }
    red[tid] = z; red2[tid] = zm;
    __syncthreads();
    for (int o = 128; o > 0; o >>= 1) {
        if (tid < o) { red[tid] += red[tid + o]; red2[tid] += red2[tid + o]; }
        __syncthreads();
    }
    z = red[0]; zm = red2[0];

    const float inv = 1.f / (zm + 1e-6f * z);
    for (int s = tid; s < SS; s += 256) {
        float e = (s < len) ? expf(sc[s] - m) * inv : 0.f;
        g_attn[(size_t)b * SS + s] = e;
    }
}

// ---------------------------------------------------------------------------
// pooling partials: float4 loads, 128 threads cover 512 cols, 8 FMA chains.
// ---------------------------------------------------------------------------
__global__ __launch_bounds__(128) void pool_kernel(
    const float* __restrict__ X, const int* __restrict__ seqlen)
{
    const int b = blockIdx.x, c = blockIdx.y;
    const int h4 = threadIdx.x * 4;          // 128 threads * 4 cols
    const int s0 = c * SCHUNK;
    const int len = seqlen[b];

    __shared__ float at[SCHUNK];
    at[threadIdx.x] = g_attn[(size_t)b * SS + s0 + threadIdx.x];
    __syncthreads();

    int end = len - s0;
    if (end > SCHUNK) end = SCHUNK;
    float4 a0 = make_float4(0.f, 0.f, 0.f, 0.f);
    float4 a1 = make_float4(0.f, 0.f, 0.f, 0.f);
    if (end > 0) {
        const float* xp = &X[((size_t)b * SS + s0) * HH + h4];
        int s = 0;
        for (; s + 1 < end; s += 2) {
            float4 x0 = *(const float4*)(xp + (size_t)s * HH);
            float4 x1 = *(const float4*)(xp + (size_t)(s + 1) * HH);
            float w0 = at[s], w1 = at[s + 1];
            a0.x = fmaf(x0.x, w0, a0.x); a0.y = fmaf(x0.y, w0, a0.y);
            a0.z = fmaf(x0.z, w0, a0.z); a0.w = fmaf(x0.w, w0, a0.w);
            a1.x = fmaf(x1.x, w1, a1.x); a1.y = fmaf(x1.y, w1, a1.y);
            a1.z = fmaf(x1.z, w1, a1.z); a1.w = fmaf(x1.w, w1, a1.w);
        }
        if (s < end) {
            float4 x0 = *(const float4*)(xp + (size_t)s * HH);
            float w0 = at[s];
            a0.x = fmaf(x0.x, w0, a0.x); a0.y = fmaf(x0.y, w0, a0.y);
            a0.z = fmaf(x0.z, w0, a0.z); a0.w = fmaf(x0.w, w0, a0.w);
        }
    }
    float4 o = make_float4(a0.x + a1.x, a0.y + a1.y, a0.z + a1.z, a0.w + a1.w);
    *(float4*)&g_pout[((size_t)b * NCHUNK + c) * HH + h4] = o;
}

__global__ __launch_bounds__(256) void reduce_out_kernel(float* __restrict__ out)
{
    int i = blockIdx.x * blockDim.x + threadIdx.x;
    if (i >= BB * HH) return;
    int b = i / HH, h = i % HH;
    float v = 0.f;
    #pragma unroll
    for (int c = 0; c < NCHUNK; c++)
        v += g_pout[((size_t)b * NCHUNK + c) * HH + h];
    out[i] = v;
}

// ---------------------------------------------------------------------------
extern "C" void kernel_launch(void* const* d_in, const int* in_sizes, int n_in,
                              void* d_out, int out_size)
{
    const float* X      = (const float*)d_in[0];
    const int*   seqlen = (const int*)  d_in[1];
    const float* W      = (const float*)d_in[2];
    const float* bias   = (const float*)d_in[3];
    const float* wat    = (const float*)d_in[4];
    float*       out    = (float*)d_out;

    cudaFuncSetAttribute(gemm_score_mma,
                         cudaFuncAttributeMaxDynamicSharedMemorySize, SMTOTAL);

    prep_w<<<dim3(16, 16), dim3(32, 8)>>>(W);

    gemm_score_mma<<<MM / BM, 512, SMTOTAL>>>(X, bias, wat);

    softmax_kernel<<<BB, 256>>>(seqlen);

    dim3 gpool(BB, NCHUNK);                  // (64, 16)
    pool_kernel<<<gpool, 128>>>(X, seqlen);

    reduce_out_kernel<<<(BB * HH + 255) / 256, 256>>>(out);
}

// round 12
// speedup vs baseline: 1.1156x; 1.0148x over previous
#include <cuda_runtime.h>
#include <cuda_fp16.h>
#include <math.h>
#include <stdint.h>

// ---------------- problem constants ----------------
#define BB 64
#define SS 2048
#define HH 512
#define MM (BB * SS)            // 131072 rows
#define BM 64
#define BN 512
#define BK 64
#define NKC (HH / BK)           // 8 k-chunks

#define SCHUNK 64
#define NCHUNK (SS / SCHUNK)    // 32

// SMEM layout (bytes). Rows padded to 144 B -> conflict-free ldmatrix phases.
#define RS    144
#define AOFF  0
#define BOFF  (BM * RS)             // 9216
#define STAGE ((BM + BN) * RS)      // 82944
#define REDOFF (2 * STAGE)          // 165888
#define SMTOTAL (REDOFF + BM * 16 * 4)  // 169984

// ---------------- scratch (static device mem) ----------------
__device__ float g_part[MM];
__device__ float g_attn[MM];
__device__ float g_pout[BB * NCHUNK * HH];
__device__ __half g_Wh[HH * HH];    // Wt[n,k] = fp16(W[k,n])

// ---------------- helpers ----------------
__device__ __forceinline__ uint32_t smem_u32(const void* p) {
    uint32_t a;
    asm("{ .reg .u64 t; cvta.to.shared.u64 t, %1; cvt.u32.u64 %0, t; }"
        : "=r"(a) : "l"(p));
    return a;
}
__device__ __forceinline__ void cpa16(uint32_t dst, const void* src) {
    asm volatile("cp.async.cg.shared.global [%0], [%1], 16;"
                 :: "r"(dst), "l"(src) : "memory");
}
__device__ __forceinline__ void mma_f16(float* d, const uint32_t* a, const uint32_t* b) {
    asm volatile("mma.sync.aligned.m16n8k16.row.col.f32.f16.f16.f32 "
                 "{%0,%1,%2,%3}, {%4,%5,%6,%7}, {%8,%9}, {%0,%1,%2,%3};"
                 : "+f"(d[0]), "+f"(d[1]), "+f"(d[2]), "+f"(d[3])
                 : "r"(a[0]), "r"(a[1]), "r"(a[2]), "r"(a[3]),
                   "r"(b[0]), "r"(b[1]));
}
__device__ __forceinline__ void ldsm4(uint32_t& r0, uint32_t& r1, uint32_t& r2,
                                      uint32_t& r3, uint32_t addr) {
    asm volatile("ldmatrix.sync.aligned.m8n8.x4.shared.b16 {%0,%1,%2,%3}, [%4];"
                 : "=r"(r0), "=r"(r1), "=r"(r2), "=r"(r3) : "r"(addr));
}
__device__ __forceinline__ uint32_t pack_h2(float x, float y) {
    __half2 h = __floats2half2_rn(x, y);
    return *(uint32_t*)&h;
}
__device__ __forceinline__ float tanh_fast(float x) {
    float y;
    asm("tanh.approx.f32 %0, %1;" : "=f"(y) : "f"(x));
    return y;
}

// ---------------------------------------------------------------------------
// W prep: transpose + fp16 round.  Wt[n,k] = fp16(W[k,n])
// ---------------------------------------------------------------------------
__global__ void prep_w(const float* __restrict__ W) {
    __shared__ float t[32][33];
    int n0 = blockIdx.x * 32, k0 = blockIdx.y * 32;
    int tx = threadIdx.x, ty = threadIdx.y;      // 32 x 8
    #pragma unroll
    for (int r = 0; r < 32; r += 8)
        t[ty + r][tx] = W[(size_t)(k0 + ty + r) * HH + n0 + tx];
    __syncthreads();
    #pragma unroll
    for (int r = 0; r < 32; r += 8) {
        int n = n0 + ty + r, k = k0 + tx;
        g_Wh[(size_t)n * HH + k] = __float2half_rn(t[tx][ty + r]);
    }
}

// ---------------------------------------------------------------------------
// fp16 HMMA GEMM, single N-pass (BN=512). X read fp32 ONCE, cvt in-register.
// grid (MM/BM) = 2048, 512 threads (16 warps across N, warp tile 64x32).
// ---------------------------------------------------------------------------
__global__ __launch_bounds__(512, 1) void gemm_score_mma(
    const float* __restrict__ A, const float* __restrict__ bias,
    const float* __restrict__ wat)
{
    extern __shared__ char sm[];
    const uint32_t sbase = smem_u32(sm);
    const int tid = threadIdx.x, lane = tid & 31, wid = tid >> 5;
    const int g = lane >> 2, tig = lane & 3;
    const int wn = wid;                     // 16 warps across N
    const int m0 = blockIdx.x * BM;

    // A fill mapping: r = tid>>3 (0..63), seg = tid&7 (0..7) -> 8 floats
    const int ar = tid >> 3, aseg = tid & 7;

    // ldmatrix lane-address offsets (within a stage)
    const uint32_t boff = (uint32_t)(BOFF + (wn * 32 + ((lane >> 4) * 8) + (lane & 7)) * RS
                                     + (((lane >> 3) & 1) * 16));
    const uint32_t aoff = (uint32_t)(AOFF + ((((lane >> 3) & 1) * 8) + (lane & 7)) * RS
                                     + ((lane >> 4) * 16));

    float acc[4][4][4] = {};   // [mi][ni][frag]

    // fill: A (fp32 load + cvt + STS), B (cp.async), one chunk into stage st
    auto fill = [&](int c, uint32_t st) {
        const int k0 = c * BK;
        #pragma unroll
        for (int t = 0; t < 8; t++) {
            int i = tid + t * 512;
            int r = i >> 3, seg = i & 7;
            cpa16(st + BOFF + r * RS + seg * 16,
                  g_Wh + (size_t)r * HH + k0 + seg * 8);
        }
        asm volatile("cp.async.commit_group;" ::: "memory");
        const float* p = &A[(size_t)(m0 + ar) * HH + k0 + aseg * 8];
        float4 v0 = *(const float4*)p;
        float4 v1 = *(const float4*)(p + 4);
        uint4 hp = make_uint4(pack_h2(v0.x, v0.y), pack_h2(v0.z, v0.w),
                              pack_h2(v1.x, v1.y), pack_h2(v1.z, v1.w));
        *(uint4*)(sm + (st - sbase) + AOFF + ar * RS + aseg * 16) = hp;
    };

    fill(0, sbase);
    asm volatile("cp.async.wait_group 0;" ::: "memory");
    __syncthreads();

    for (int c = 0; c < NKC; c++) {
        const int pb = c & 1, nb = pb ^ 1;
        if (c + 1 < NKC) fill(c + 1, sbase + nb * STAGE);

        const uint32_t st = sbase + pb * STAGE;
        #pragma unroll
        for (int ks = 0; ks < 4; ks++) {
            const uint32_t kso = (uint32_t)(ks * 32);
            uint32_t bh[4][2];
            ldsm4(bh[0][0], bh[0][1], bh[1][0], bh[1][1], st + boff + kso);
            ldsm4(bh[2][0], bh[2][1], bh[3][0], bh[3][1], st + boff + kso + 16 * RS);
            #pragma unroll
            for (int mi = 0; mi < 4; mi++) {
                uint32_t ah[4];
                ldsm4(ah[0], ah[1], ah[2], ah[3],
                      st + aoff + (uint32_t)(mi * 16 * RS) + kso);
                #pragma unroll
                for (int ni = 0; ni < 4; ni++)
                    mma_f16(acc[mi][ni], ah, bh[ni]);
            }
        }

        if (c + 1 < NKC) {
            asm volatile("cp.async.wait_group 0;" ::: "memory");
            __syncthreads();
        }
    }

    // ---- epilogue: tanh.approx(z + b) * w, reduce over ALL 512 columns ----
    float bbx[4], bby[4], wwx[4], wwy[4];
    #pragma unroll
    for (int ni = 0; ni < 4; ni++) {
        int col = wn * 32 + ni * 8 + tig * 2;
        float2 bb = *(const float2*)&bias[col];
        float2 ww = *(const float2*)&wat[col];
        bbx[ni] = bb.x; bby[ni] = bb.y; wwx[ni] = ww.x; wwy[ni] = ww.y;
    }
    float* red = (float*)(sm + REDOFF);   // [64 rows][16 warps]
    #pragma unroll
    for (int mi = 0; mi < 4; mi++) {
        float s0 = 0.f, s1 = 0.f;
        #pragma unroll
        for (int ni = 0; ni < 4; ni++) {
            s0 += tanh_fast(acc[mi][ni][0] + bbx[ni]) * wwx[ni]
                + tanh_fast(acc[mi][ni][1] + bby[ni]) * wwy[ni];
            s1 += tanh_fast(acc[mi][ni][2] + bbx[ni]) * wwx[ni]
                + tanh_fast(acc[mi][ni][3] + bby[ni]) * wwy[ni];
        }
        s0 += __shfl_down_sync(0xFFFFFFFFu, s0, 2, 4);
        s0 += __shfl_down_sync(0xFFFFFFFFu, s0, 1, 4);
        s1 += __shfl_down_sync(0xFFFFFFFFu, s1, 2, 4);
        s1 += __shfl_down_sync(0xFFFFFFFFu, s1, 1, 4);
        if (tig == 0) {
            red[(mi * 16 + g) * 16 + wn]     = s0;
            red[(mi * 16 + 8 + g) * 16 + wn] = s1;
        }
    }
    __syncthreads();
    if (tid < BM) {
        const float* r = red + tid * 16;
        float v = 0.f;
        #pragma unroll
        for (int j = 0; j < 16; j++) v += r[j];
        g_part[(size_t)m0 + tid] = v;
    }
}

// ---------------------------------------------------------------------------
// softmax over full sequence, then mask + renormalize.
// ---------------------------------------------------------------------------
__global__ __launch_bounds__(256) void softmax_kernel(const int* __restrict__ seqlen)
{
    __shared__ float sc[SS];
    __shared__ float red[256];
    __shared__ float red2[256];

    const int b = blockIdx.x, tid = threadIdx.x;
    const int len = seqlen[b];

    for (int s = tid; s < SS; s += 256)
        sc[s] = g_part[(size_t)b * SS + s];
    __syncthreads();

    float m = -INFINITY;
    for (int s = tid; s < SS; s += 256) m = fmaxf(m, sc[s]);
    red[tid] = m;
    __syncthreads();
    for (int o = 128; o > 0; o >>= 1) {
        if (tid < o) red[tid] = fmaxf(red[tid], red[tid + o]);
        __syncthreads();
    }
    m = red[0];
    __syncthreads();

    float z = 0.f, zm = 0.f;
    for (int s = tid; s < SS; s += 256) {
        float e = expf(sc[s] - m);
        z += e;
        if (s < len) zm += e;
    }
    red[tid] = z; red2[tid] = zm;
    __syncthreads();
    for (int o = 128; o > 0; o >>= 1) {
        if (tid < o) { red[tid] += red[tid + o]; red2[tid] += red2[tid + o]; }
        __syncthreads();
    }
    z = red[0]; zm = red2[0];

    const float inv = 1.f / (zm + 1e-6f * z);
    for (int s = tid; s < SS; s += 256) {
        float e = (s < len) ? expf(sc[s] - m) * inv : 0.f;
        g_attn[(size_t)b * SS + s] = e;
    }
}

// ---------------------------------------------------------------------------
// pooling partials: float4 streaming loads, SCHUNK=64 for occupancy/balance.
// grid (BB, NCHUNK) = (64, 32), 128 threads.
// ---------------------------------------------------------------------------
__global__ __launch_bounds__(128) void pool_kernel(
    const float* __restrict__ X, const int* __restrict__ seqlen)
{
    const int b = blockIdx.x, c = blockIdx.y;
    const int h4 = threadIdx.x * 4;          // 128 threads * 4 cols
    const int s0 = c * SCHUNK;
    const int len = seqlen[b];

    __shared__ float at[SCHUNK];
    if (threadIdx.x < SCHUNK)
        at[threadIdx.x] = g_attn[(size_t)b * SS + s0 + threadIdx.x];
    __syncthreads();

    int end = len - s0;
    if (end > SCHUNK) end = SCHUNK;
    float4 a0 = make_float4(0.f, 0.f, 0.f, 0.f);
    float4 a1 = make_float4(0.f, 0.f, 0.f, 0.f);
    if (end > 0) {
        const float* xp = &X[((size_t)b * SS + s0) * HH + h4];
        int s = 0;
        for (; s + 1 < end; s += 2) {
            float4 x0 = __ldcs((const float4*)(xp + (size_t)s * HH));
            float4 x1 = __ldcs((const float4*)(xp + (size_t)(s + 1) * HH));
            float w0 = at[s], w1 = at[s + 1];
            a0.x = fmaf(x0.x, w0, a0.x); a0.y = fmaf(x0.y, w0, a0.y);
            a0.z = fmaf(x0.z, w0, a0.z); a0.w = fmaf(x0.w, w0, a0.w);
            a1.x = fmaf(x1.x, w1, a1.x); a1.y = fmaf(x1.y, w1, a1.y);
            a1.z = fmaf(x1.z, w1, a1.z); a1.w = fmaf(x1.w, w1, a1.w);
        }
        if (s < end) {
            float4 x0 = __ldcs((const float4*)(xp + (size_t)s * HH));
            float w0 = at[s];
            a0.x = fmaf(x0.x, w0, a0.x); a0.y = fmaf(x0.y, w0, a0.y);
            a0.z = fmaf(x0.z, w0, a0.z); a0.w = fmaf(x0.w, w0, a0.w);
        }
    }
    float4 o = make_float4(a0.x + a1.x, a0.y + a1.y, a0.z + a1.z, a0.w + a1.w);
    *(float4*)&g_pout[((size_t)b * NCHUNK + c) * HH + h4] = o;
}

// ---------------------------------------------------------------------------
// reduce pooling partials -> out[b, h], float4.
// ---------------------------------------------------------------------------
__global__ __launch_bounds__(256) void reduce_out_kernel(float* __restrict__ out)
{
    int i = blockIdx.x * blockDim.x + threadIdx.x;   // over BB*HH/4
    if (i >= BB * HH / 4) return;
    int b = i / (HH / 4), q = i % (HH / 4);
    const float4* p = (const float4*)g_pout + (size_t)b * NCHUNK * (HH / 4) + q;
    float4 v = make_float4(0.f, 0.f, 0.f, 0.f);
    #pragma unroll
    for (int c = 0; c < NCHUNK; c++) {
        float4 x = p[(size_t)c * (HH / 4)];
        v.x += x.x; v.y += x.y; v.z += x.z; v.w += x.w;
    }
    ((float4*)out)[i] = v;
}

// ---------------------------------------------------------------------------
extern "C" void kernel_launch(void* const* d_in, const int* in_sizes, int n_in,
                              void* d_out, int out_size)
{
    const float* X      = (const float*)d_in[0];
    const int*   seqlen = (const int*)  d_in[1];
    const float* W      = (const float*)d_in[2];
    const float* bias   = (const float*)d_in[3];
    const float* wat    = (const float*)d_in[4];
    float*       out    = (float*)d_out;

    cudaFuncSetAttribute(gemm_score_mma,
                         cudaFuncAttributeMaxDynamicSharedMemorySize, SMTOTAL);

    prep_w<<<dim3(16, 16), dim3(32, 8)>>>(W);

    gemm_score_mma<<<MM / BM, 512, SMTOTAL>>>(X, bias, wat);

    softmax_kernel<<<BB, 256>>>(seqlen);

    dim3 gpool(BB, NCHUNK);                  // (64, 32)
    pool_kernel<<<gpool, 128>>>(X, seqlen);

    reduce_out_kernel<<<(BB * HH / 4 + 255) / 256, 256>>>(out);
}

// round 13
// speedup vs baseline: 1.1310x; 1.0138x over previous
#include <cuda_runtime.h>
#include <cuda_fp16.h>
#include <math.h>
#include <stdint.h>

// ---------------- problem constants ----------------
#define BB 64
#define SS 2048
#define HH 512
#define MM (BB * SS)            // 131072 rows
#define BM 64
#define BN 512
#define BK 64
#define NKC (HH / BK)           // 8 k-chunks

#define SCHUNK 64
#define NCHUNK (SS / SCHUNK)    // 32

// SMEM layout (bytes). Rows padded to 144 B -> conflict-free ldmatrix phases.
#define RS    144
#define AOFF  0
#define BOFF  (BM * RS)             // 9216
#define STAGE ((BM + BN) * RS)      // 82944
#define REDOFF (2 * STAGE)          // 165888
#define SMTOTAL (REDOFF + BM * 16 * 4)  // 169984

// ---------------- scratch (static device mem) ----------------
__device__ float g_part[MM];
__device__ float g_attn[MM];
__device__ float g_pout[BB * NCHUNK * HH];
__device__ __half g_Wh[HH * HH];    // Wt[n,k] = fp16(W[k,n])

// ---------------- helpers ----------------
__device__ __forceinline__ uint32_t smem_u32(const void* p) {
    uint32_t a;
    asm("{ .reg .u64 t; cvta.to.shared.u64 t, %1; cvt.u32.u64 %0, t; }"
        : "=r"(a) : "l"(p));
    return a;
}
__device__ __forceinline__ void cpa16(uint32_t dst, const void* src) {
    asm volatile("cp.async.cg.shared.global [%0], [%1], 16;"
                 :: "r"(dst), "l"(src) : "memory");
}
__device__ __forceinline__ void mma_f16(float* d, const uint32_t* a, const uint32_t* b) {
    asm volatile("mma.sync.aligned.m16n8k16.row.col.f32.f16.f16.f32 "
                 "{%0,%1,%2,%3}, {%4,%5,%6,%7}, {%8,%9}, {%0,%1,%2,%3};"
                 : "+f"(d[0]), "+f"(d[1]), "+f"(d[2]), "+f"(d[3])
                 : "r"(a[0]), "r"(a[1]), "r"(a[2]), "r"(a[3]),
                   "r"(b[0]), "r"(b[1]));
}
__device__ __forceinline__ void ldsm4(uint32_t& r0, uint32_t& r1, uint32_t& r2,
                                      uint32_t& r3, uint32_t addr) {
    asm volatile("ldmatrix.sync.aligned.m8n8.x4.shared.b16 {%0,%1,%2,%3}, [%4];"
                 : "=r"(r0), "=r"(r1), "=r"(r2), "=r"(r3) : "r"(addr));
}
__device__ __forceinline__ uint32_t pack_h2(float x, float y) {
    __half2 h = __floats2half2_rn(x, y);
    return *(uint32_t*)&h;
}
__device__ __forceinline__ float tanh_fast(float x) {
    float y;
    asm("tanh.approx.f32 %0, %1;" : "=f"(y) : "f"(x));
    return y;
}

// ---------------------------------------------------------------------------
// W prep: transpose + fp16 round.  Wt[n,k] = fp16(W[k,n])
// ---------------------------------------------------------------------------
__global__ void prep_w(const float* __restrict__ W) {
    __shared__ float t[32][33];
    int n0 = blockIdx.x * 32, k0 = blockIdx.y * 32;
    int tx = threadIdx.x, ty = threadIdx.y;      // 32 x 8
    #pragma unroll
    for (int r = 0; r < 32; r += 8)
        t[ty + r][tx] = W[(size_t)(k0 + ty + r) * HH + n0 + tx];
    __syncthreads();
    #pragma unroll
    for (int r = 0; r < 32; r += 8) {
        int n = n0 + ty + r, k = k0 + tx;
        g_Wh[(size_t)n * HH + k] = __float2half_rn(t[tx][ty + r]);
    }
}

// ---------------------------------------------------------------------------
// fp16 HMMA GEMM, single N-pass (BN=512). X read fp32 ONCE, cvt in-register.
// grid (MM/BM) = 2048, 512 threads (16 warps across N, warp tile 64x32).
// FROZEN: best-measured mainloop (R8/R11). Do not touch.
// ---------------------------------------------------------------------------
__global__ __launch_bounds__(512, 1) void gemm_score_mma(
    const float* __restrict__ A, const float* __restrict__ bias,
    const float* __restrict__ wat)
{
    extern __shared__ char sm[];
    const uint32_t sbase = smem_u32(sm);
    const int tid = threadIdx.x, lane = tid & 31, wid = tid >> 5;
    const int g = lane >> 2, tig = lane & 3;
    const int wn = wid;                     // 16 warps across N
    const int m0 = blockIdx.x * BM;

    const int ar = tid >> 3, aseg = tid & 7;

    const uint32_t boff = (uint32_t)(BOFF + (wn * 32 + ((lane >> 4) * 8) + (lane & 7)) * RS
                                     + (((lane >> 3) & 1) * 16));
    const uint32_t aoff = (uint32_t)(AOFF + ((((lane >> 3) & 1) * 8) + (lane & 7)) * RS
                                     + ((lane >> 4) * 16));

    float acc[4][4][4] = {};   // [mi][ni][frag]

    auto fill = [&](int c, uint32_t st) {
        const int k0 = c * BK;
        #pragma unroll
        for (int t = 0; t < 8; t++) {
            int i = tid + t * 512;
            int r = i >> 3, seg = i & 7;
            cpa16(st + BOFF + r * RS + seg * 16,
                  g_Wh + (size_t)r * HH + k0 + seg * 8);
        }
        asm volatile("cp.async.commit_group;" ::: "memory");
        const float* p = &A[(size_t)(m0 + ar) * HH + k0 + aseg * 8];
        float4 v0 = *(const float4*)p;
        float4 v1 = *(const float4*)(p + 4);
        uint4 hp = make_uint4(pack_h2(v0.x, v0.y), pack_h2(v0.z, v0.w),
                              pack_h2(v1.x, v1.y), pack_h2(v1.z, v1.w));
        *(uint4*)(sm + (st - sbase) + AOFF + ar * RS + aseg * 16) = hp;
    };

    fill(0, sbase);
    asm volatile("cp.async.wait_group 0;" ::: "memory");
    __syncthreads();

    for (int c = 0; c < NKC; c++) {
        const int pb = c & 1, nb = pb ^ 1;
        if (c + 1 < NKC) fill(c + 1, sbase + nb * STAGE);

        const uint32_t st = sbase + pb * STAGE;
        #pragma unroll
        for (int ks = 0; ks < 4; ks++) {
            const uint32_t kso = (uint32_t)(ks * 32);
            uint32_t bh[4][2];
            ldsm4(bh[0][0], bh[0][1], bh[1][0], bh[1][1], st + boff + kso);
            ldsm4(bh[2][0], bh[2][1], bh[3][0], bh[3][1], st + boff + kso + 16 * RS);
            #pragma unroll
            for (int mi = 0; mi < 4; mi++) {
                uint32_t ah[4];
                ldsm4(ah[0], ah[1], ah[2], ah[3],
                      st + aoff + (uint32_t)(mi * 16 * RS) + kso);
                #pragma unroll
                for (int ni = 0; ni < 4; ni++)
                    mma_f16(acc[mi][ni], ah, bh[ni]);
            }
        }

        if (c + 1 < NKC) {
            asm volatile("cp.async.wait_group 0;" ::: "memory");
            __syncthreads();
        }
    }

    // ---- epilogue: tanh.approx(z + b) * w, reduce over ALL 512 columns ----
    float bbx[4], bby[4], wwx[4], wwy[4];
    #pragma unroll
    for (int ni = 0; ni < 4; ni++) {
        int col = wn * 32 + ni * 8 + tig * 2;
        float2 bb = *(const float2*)&bias[col];
        float2 ww = *(const float2*)&wat[col];
        bbx[ni] = bb.x; bby[ni] = bb.y; wwx[ni] = ww.x; wwy[ni] = ww.y;
    }
    float* red = (float*)(sm + REDOFF);   // [64 rows][16 warps]
    #pragma unroll
    for (int mi = 0; mi < 4; mi++) {
        float s0 = 0.f, s1 = 0.f;
        #pragma unroll
        for (int ni = 0; ni < 4; ni++) {
            s0 += tanh_fast(acc[mi][ni][0] + bbx[ni]) * wwx[ni]
                + tanh_fast(acc[mi][ni][1] + bby[ni]) * wwy[ni];
            s1 += tanh_fast(acc[mi][ni][2] + bbx[ni]) * wwx[ni]
                + tanh_fast(acc[mi][ni][3] + bby[ni]) * wwy[ni];
        }
        s0 += __shfl_down_sync(0xFFFFFFFFu, s0, 2, 4);
        s0 += __shfl_down_sync(0xFFFFFFFFu, s0, 1, 4);
        s1 += __shfl_down_sync(0xFFFFFFFFu, s1, 2, 4);
        s1 += __shfl_down_sync(0xFFFFFFFFu, s1, 1, 4);
        if (tig == 0) {
            red[(mi * 16 + g) * 16 + wn]     = s0;
            red[(mi * 16 + 8 + g) * 16 + wn] = s1;
        }
    }
    __syncthreads();
    if (tid < BM) {
        const float* r = red + tid * 16;
        float v = 0.f;
        #pragma unroll
        for (int j = 0; j < 16; j++) v += r[j];
        g_part[(size_t)m0 + tid] = v;
    }
}

// ---------------------------------------------------------------------------
// softmax over full sequence, then mask + renormalize. 512 threads.
// ---------------------------------------------------------------------------
__global__ __launch_bounds__(512) void softmax_kernel(const int* __restrict__ seqlen)
{
    __shared__ float sc[SS];
    __shared__ float red[512];
    __shared__ float red2[512];

    const int b = blockIdx.x, tid = threadIdx.x;
    const int len = seqlen[b];

    for (int s = tid; s < SS; s += 512)
        sc[s] = g_part[(size_t)b * SS + s];
    __syncthreads();

    float m = fmaxf(sc[tid], sc[tid + 512]);
    m = fmaxf(m, fmaxf(sc[tid + 1024], sc[tid + 1536]));
    red[tid] = m;
    __syncthreads();
    for (int o = 256; o > 0; o >>= 1) {
        if (tid < o) red[tid] = fmaxf(red[tid], red[tid + o]);
        __syncthreads();
    }
    m = red[0];
    __syncthreads();

    float z = 0.f, zm = 0.f;
    #pragma unroll
    for (int t = 0; t < 4; t++) {
        int s = tid + t * 512;
        float e = expf(sc[s] - m);
        z += e;
        if (s < len) zm += e;
    }
    red[tid] = z; red2[tid] = zm;
    __syncthreads();
    for (int o = 256; o > 0; o >>= 1) {
        if (tid < o) { red[tid] += red[tid + o]; red2[tid] += red2[tid + o]; }
        __syncthreads();
    }
    z = red[0]; zm = red2[0];

    const float inv = 1.f / (zm + 1e-6f * z);
    #pragma unroll
    for (int t = 0; t < 4; t++) {
        int s = tid + t * 512;
        float e = (s < len) ? expf(sc[s] - m) * inv : 0.f;
        g_attn[(size_t)b * SS + s] = e;
    }
}

// ---------------------------------------------------------------------------
// pooling partials: 4 in-flight streaming float4 loads, 4 accumulators.
// grid (BB, NCHUNK) = (64, 32), 128 threads.
// ---------------------------------------------------------------------------
__global__ __launch_bounds__(128) void pool_kernel(
    const float* __restrict__ X, const int* __restrict__ seqlen)
{
    const int b = blockIdx.x, c = blockIdx.y;
    const int h4 = threadIdx.x * 4;          // 128 threads * 4 cols
    const int s0 = c * SCHUNK;
    const int len = seqlen[b];

    int end = len - s0;
    if (end > SCHUNK) end = SCHUNK;
    if (end <= 0) {                          // fully masked: zeros, early out
        *(float4*)&g_pout[((size_t)b * NCHUNK + c) * HH + h4] =
            make_float4(0.f, 0.f, 0.f, 0.f);
        return;
    }

    __shared__ float at[SCHUNK];
    if (threadIdx.x < SCHUNK)
        at[threadIdx.x] = g_attn[(size_t)b * SS + s0 + threadIdx.x];
    __syncthreads();

    float4 a0 = make_float4(0.f, 0.f, 0.f, 0.f);
    float4 a1 = make_float4(0.f, 0.f, 0.f, 0.f);
    float4 a2 = make_float4(0.f, 0.f, 0.f, 0.f);
    float4 a3 = make_float4(0.f, 0.f, 0.f, 0.f);
    const float* xp = &X[((size_t)b * SS + s0) * HH + h4];
    int s = 0;
    for (; s + 3 < end; s += 4) {
        float4 x0 = __ldcs((const float4*)(xp + (size_t)(s + 0) * HH));
        float4 x1 = __ldcs((const float4*)(xp + (size_t)(s + 1) * HH));
        float4 x2 = __ldcs((const float4*)(xp + (size_t)(s + 2) * HH));
        float4 x3 = __ldcs((const float4*)(xp + (size_t)(s + 3) * HH));
        float w0 = at[s], w1 = at[s + 1], w2 = at[s + 2], w3 = at[s + 3];
        a0.x = fmaf(x0.x, w0, a0.x); a0.y = fmaf(x0.y, w0, a0.y);
        a0.z = fmaf(x0.z, w0, a0.z); a0.w = fmaf(x0.w, w0, a0.w);
        a1.x = fmaf(x1.x, w1, a1.x); a1.y = fmaf(x1.y, w1, a1.y);
        a1.z = fmaf(x1.z, w1, a1.z); a1.w = fmaf(x1.w, w1, a1.w);
        a2.x = fmaf(x2.x, w2, a2.x); a2.y = fmaf(x2.y, w2, a2.y);
        a2.z = fmaf(x2.z, w2, a2.z); a2.w = fmaf(x2.w, w2, a2.w);
        a3.x = fmaf(x3.x, w3, a3.x); a3.y = fmaf(x3.y, w3, a3.y);
        a3.z = fmaf(x3.z, w3, a3.z); a3.w = fmaf(x3.w, w3, a3.w);
    }
    for (; s < end; s++) {
        float4 x0 = __ldcs((const float4*)(xp + (size_t)s * HH));
        float w0 = at[s];
        a0.x = fmaf(x0.x, w0, a0.x); a0.y = fmaf(x0.y, w0, a0.y);
        a0.z = fmaf(x0.z, w0, a0.z); a0.w = fmaf(x0.w, w0, a0.w);
    }
    float4 o = make_float4((a0.x + a1.x) + (a2.x + a3.x),
                           (a0.y + a1.y) + (a2.y + a3.y),
                           (a0.z + a1.z) + (a2.z + a3.z),
                           (a0.w + a1.w) + (a2.w + a3.w));
    *(float4*)&g_pout[((size_t)b * NCHUNK + c) * HH + h4] = o;
}

// ---------------------------------------------------------------------------
// reduce pooling partials -> out[b, h], float4.
// ---------------------------------------------------------------------------
__global__ __launch_bounds__(256) void reduce_out_kernel(float* __restrict__ out)
{
    int i = blockIdx.x * blockDim.x + threadIdx.x;   // over BB*HH/4
    if (i >= BB * HH / 4) return;
    int b = i / (HH / 4), q = i % (HH / 4);
    const float4* p = (const float4*)g_pout + (size_t)b * NCHUNK * (HH / 4) + q;
    float4 v = make_float4(0.f, 0.f, 0.f, 0.f);
    #pragma unroll
    for (int c = 0; c < NCHUNK; c++) {
        float4 x = p[(size_t)c * (HH / 4)];
        v.x += x.x; v.y += x.y; v.z += x.z; v.w += x.w;
    }
    ((float4*)out)[i] = v;
}

// ---------------------------------------------------------------------------
extern "C" void kernel_launch(void* const* d_in, const int* in_sizes, int n_in,
                              void* d_out, int out_size)
{
    const float* X      = (const float*)d_in[0];
    const int*   seqlen = (const int*)  d_in[1];
    const float* W      = (const float*)d_in[2];
    const float* bias   = (const float*)d_in[3];
    const float* wat    = (const float*)d_in[4];
    float*       out    = (float*)d_out;

    cudaFuncSetAttribute(gemm_score_mma,
                         cudaFuncAttributeMaxDynamicSharedMemorySize, SMTOTAL);

    prep_w<<<dim3(16, 16), dim3(32, 8)>>>(W);

    gemm_score_mma<<<MM / BM, 512, SMTOTAL>>>(X, bias, wat);

    softmax_kernel<<<BB, 512>>>(seqlen);

    dim3 gpool(BB, NCHUNK);                  // (64, 32)
    pool_kernel<<<gpool, 128>>>(X, seqlen);

    reduce_out_kernel<<<(BB * HH / 4 + 255) / 256, 256>>>(out);
}